// round 5
// baseline (speedup 1.0000x reference)
#include <cuda_runtime.h>
#include <cuda_bf16.h>
#include <cstdint>

// Problem constants (fixed by setup_inputs)
#define B_    4
#define NC    4096      // coarse points per batch
#define MF    16384     // fine points per batch
#define CIN   384
#define COUT  192
#define NTOT  (B_*NC)   // 16384
#define MTOT  (B_*MF)   // 65536

// Scratch (static device globals; allocation-free)
__device__ float g_h[NTOT * COUT];          // branch-2 features at coarse points
__device__ int   g_idx[MTOT * 3];           // 3-NN indices (global coarse index)
__device__ float g_wgt[MTOT * 3];           // 3-NN inverse-distance weights
__device__ float g_stat_f[NTOT * 2];        // per-row (mu, rstd) feats
__device__ float g_stat_s[MTOT * 2];        // per-row (mu, rstd) support_feats
__device__ __nv_bfloat16 g_w2hi[COUT * CIN];   // gamma-folded, transposed [N][K]
__device__ __nv_bfloat16 g_w2lo[COUT * CIN];
__device__ __nv_bfloat16 g_w1hi[COUT * COUT];
__device__ __nv_bfloat16 g_w1lo[COUT * COUT];
__device__ float g_b2p[COUT];               // beta-folded biases
__device__ float g_b1p[COUT];

// ---------------------------------------------------------------------------
// MMA helpers (baseline PTX, sm_80+: works on compute_103 target)
// ---------------------------------------------------------------------------
__device__ __forceinline__ void ldsm4(uint32_t* r, uint32_t addr) {
    asm volatile("ldmatrix.sync.aligned.m8n8.x4.shared.b16 {%0,%1,%2,%3}, [%4];"
                 : "=r"(r[0]), "=r"(r[1]), "=r"(r[2]), "=r"(r[3]) : "r"(addr));
}
__device__ __forceinline__ void mma16816(float* d, const uint32_t* a, const uint32_t* b) {
    asm volatile("mma.sync.aligned.m16n8k16.row.col.f32.bf16.bf16.f32 "
                 "{%0,%1,%2,%3}, {%4,%5,%6,%7}, {%8,%9}, {%0,%1,%2,%3};"
                 : "+f"(d[0]), "+f"(d[1]), "+f"(d[2]), "+f"(d[3])
                 : "r"(a[0]), "r"(a[1]), "r"(a[2]), "r"(a[3]), "r"(b[0]), "r"(b[1]));
}
__device__ __forceinline__ uint32_t sw128(uint32_t off) { return off ^ ((off >> 3) & 0x70); }
__device__ __forceinline__ uint32_t smem_addr(const void* p) {
    return (uint32_t)__cvta_generic_to_shared(p);
}

// ---------------------------------------------------------------------------
// Per-row LN statistics: one warp per row -> (mu, rstd)
// ---------------------------------------------------------------------------
template<int C>
__global__ void stats_kernel(const float* __restrict__ x, float* __restrict__ stat, int rows)
{
    int warp = (blockIdx.x * blockDim.x + threadIdx.x) >> 5;
    if (warp >= rows) return;
    int lane = threadIdx.x & 31;
    const float* xr = x + (long)warp * C;
    float s = 0.f, ss = 0.f;
#pragma unroll
    for (int i = 0; i < C / 32; i++) {
        float v = xr[lane + i * 32];
        s += v;
        ss += v * v;
    }
#pragma unroll
    for (int o = 16; o; o >>= 1) {
        s  += __shfl_xor_sync(0xffffffffu, s,  o);
        ss += __shfl_xor_sync(0xffffffffu, ss, o);
    }
    if (lane == 0) {
        float mu  = s * (1.0f / C);
        float var = ss * (1.0f / C) - mu * mu;
        stat[warp * 2 + 0] = mu;
        stat[warp * 2 + 1] = rsqrtf(var + 1e-5f);
    }
}

// ---------------------------------------------------------------------------
// Prep: fold LN gamma into W (transposed [N][K], bf16 hi/lo split) and
// LN beta into bias. grid = 2*COUT + 2 blocks, 192 threads.
// ---------------------------------------------------------------------------
__global__ void prep_kernel(const float* __restrict__ w2, const float* __restrict__ ln2_g,
                            const float* __restrict__ ln2_b, const float* __restrict__ b2,
                            const float* __restrict__ w1, const float* __restrict__ ln1_g,
                            const float* __restrict__ ln1_b, const float* __restrict__ b1)
{
    int bid = blockIdx.x;
    int t = threadIdx.x;
    if (bid < COUT) {                         // w2 row n, K = CIN
        int n = bid;
        for (int k = t; k < CIN; k += COUT) {
            float v = ln2_g[k] * w2[k * COUT + n];
            __nv_bfloat16 hi = __float2bfloat16_rn(v);
            __nv_bfloat16 lo = __float2bfloat16_rn(v - __bfloat162float(hi));
            g_w2hi[n * CIN + k] = hi;
            g_w2lo[n * CIN + k] = lo;
        }
    } else if (bid < 2 * COUT) {              // w1 row n, K = COUT
        int n = bid - COUT;
        for (int k = t; k < COUT; k += COUT) {
            float v = ln1_g[k] * w1[k * COUT + n];
            __nv_bfloat16 hi = __float2bfloat16_rn(v);
            __nv_bfloat16 lo = __float2bfloat16_rn(v - __bfloat162float(hi));
            g_w1hi[n * COUT + k] = hi;
            g_w1lo[n * COUT + k] = lo;
        }
    } else if (bid == 2 * COUT) {
        float s = b2[t];
        for (int k = 0; k < CIN; k++) s = fmaf(ln2_b[k], w2[k * COUT + t], s);
        g_b2p[t] = s;
    } else {
        float s = b1[t];
        for (int k = 0; k < COUT; k++) s = fmaf(ln1_b[k], w1[k * COUT + t], s);
        g_b1p[t] = s;
    }
}

// ---------------------------------------------------------------------------
// Brute-force 3-NN. 2 queries per thread, 512 queries per block.
// ---------------------------------------------------------------------------
__global__ void knn_kernel(const float* __restrict__ cxyz, const float* __restrict__ qxyz)
{
    extern __shared__ char smem_c[];
    float* sx = (float*)smem_c;
    float* sy = sx + NC;
    float* sz = sx + 2 * NC;

    int bidx  = blockIdx.x >> 5;              // 32 blocks of 512 queries per batch
    int chunk = blockIdx.x & 31;
    const float* cb = cxyz + (long)bidx * NC * 3;
    for (int i = threadIdx.x; i < NC; i += 256) {
        sx[i] = cb[i * 3 + 0];
        sy[i] = cb[i * 3 + 1];
        sz[i] = cb[i * 3 + 2];
    }
    __syncthreads();

    int qA = bidx * MF + chunk * 512 + threadIdx.x;
    int qB = qA + 256;
    float ax = qxyz[qA * 3 + 0], ay = qxyz[qA * 3 + 1], az = qxyz[qA * 3 + 2];
    float bx = qxyz[qB * 3 + 0], by = qxyz[qB * 3 + 1], bz = qxyz[qB * 3 + 2];

    float a0 = 1e30f, a1 = 1e30f, a2 = 1e30f; int ai0 = 0, ai1 = 0, ai2 = 0;
    float c0 = 1e30f, c1 = 1e30f, c2 = 1e30f; int ci0 = 0, ci1 = 0, ci2 = 0;

#pragma unroll 8
    for (int j = 0; j < NC; j++) {
        float px = sx[j], py = sy[j], pz = sz[j];
        {
            float dx = ax - px, dy = ay - py, dz = az - pz;
            float d = fmaf(dz, dz, fmaf(dy, dy, dx * dx));
            if (d < a2) {
                if (d < a1) {
                    a2 = a1; ai2 = ai1;
                    if (d < a0) { a1 = a0; ai1 = ai0; a0 = d; ai0 = j; }
                    else        { a1 = d;  ai1 = j; }
                } else { a2 = d; ai2 = j; }
            }
        }
        {
            float dx = bx - px, dy = by - py, dz = bz - pz;
            float d = fmaf(dz, dz, fmaf(dy, dy, dx * dx));
            if (d < c2) {
                if (d < c1) {
                    c2 = c1; ci2 = ci1;
                    if (d < c0) { c1 = c0; ci1 = ci0; c0 = d; ci0 = j; }
                    else        { c1 = d;  ci1 = j; }
                } else { c2 = d; ci2 = j; }
            }
        }
    }

    {
        float r0 = 1.0f / (sqrtf(a0) + 1e-8f);
        float r1 = 1.0f / (sqrtf(a1) + 1e-8f);
        float r2 = 1.0f / (sqrtf(a2) + 1e-8f);
        float rs = 1.0f / (r0 + r1 + r2);
        g_idx[qA * 3 + 0] = bidx * NC + ai0;
        g_idx[qA * 3 + 1] = bidx * NC + ai1;
        g_idx[qA * 3 + 2] = bidx * NC + ai2;
        g_wgt[qA * 3 + 0] = r0 * rs;
        g_wgt[qA * 3 + 1] = r1 * rs;
        g_wgt[qA * 3 + 2] = r2 * rs;
    }
    {
        float r0 = 1.0f / (sqrtf(c0) + 1e-8f);
        float r1 = 1.0f / (sqrtf(c1) + 1e-8f);
        float r2 = 1.0f / (sqrtf(c2) + 1e-8f);
        float rs = 1.0f / (r0 + r1 + r2);
        g_idx[qB * 3 + 0] = bidx * NC + ci0;
        g_idx[qB * 3 + 1] = bidx * NC + ci1;
        g_idx[qB * 3 + 2] = bidx * NC + ci2;
        g_wgt[qB * 3 + 0] = r0 * rs;
        g_wgt[qB * 3 + 1] = r1 * rs;
        g_wgt[qB * 3 + 2] = r2 * rs;
    }
}

// ---------------------------------------------------------------------------
// bf16x3 warp-MMA GEMM: C[M,192] = LN(A)[M,K] @ W'[K,192] + b'  (+ interp)
// CTA tile 128x64, 8 warps (4 along M x 2 along N), warp tile 32x32.
// BK=64, single-stage SW128-swizzled smem, mma.sync m16n8k16 bf16, fp32 acc.
// D = Ahi*Bhi + Alo*Bhi + Ahi*Blo.
// ---------------------------------------------------------------------------
#define SO_A_HI  0
#define SO_A_LO  16384
#define SO_B_HI  32768
#define SO_B_LO  40960
#define SMEM_DYN 49152

template<int K, bool INTERP>
__global__ __launch_bounds__(256, 2)
void mma_gemm(const float* __restrict__ A, const float* __restrict__ stat,
              const __nv_bfloat16* __restrict__ Whi, const __nv_bfloat16* __restrict__ Wlo,
              const float* __restrict__ bias, float* __restrict__ C)
{
    extern __shared__ char smem_c[];
    char* sm = smem_c;

    const int t    = threadIdx.x;
    const int lane = t & 31;
    const int wid  = t >> 5;
    const int wm   = wid & 3;        // warp m-group (0..3)
    const int wn   = wid >> 2;       // warp n-group (0..1)
    const int m0   = blockIdx.y * 128;
    const int n0   = blockIdx.x * 64;

    // A loader mapping (1024 items of 8 floats)
    const int arow = t >> 1;                 // reused with +0..3*? no: per-gi below
    (void)arow;

    float d[2][4][4] = {};                   // [mi][n8-tile][reg]

    const int g8 = lane >> 3, r8 = lane & 7; // ldmatrix address groups
    // A frag addr components: row = mbase + (g8&1)*8 + r8 ; kc = (g8>>1)*8
    // B frag addr components: row(n) = nbase + (g8>>1)*8 + r8 ; kc = (g8&1)*8

#pragma unroll 1
    for (int kt = 0; kt < K / 64; kt++) {
        if (kt) __syncthreads();
        const int k0 = kt * 64;
        // --- stage A: 128 rows x 64 k -> normalized bf16 hi/lo
#pragma unroll
        for (int gi = 0; gi < 4; gi++) {
            int g   = t + 256 * gi;          // 0..1023
            int row = g >> 3;
            int kc  = (g & 7) * 8;
            const float* p = A + (long)(m0 + row) * K + k0 + kc;
            float mu   = stat[(m0 + row) * 2 + 0];
            float rstd = stat[(m0 + row) * 2 + 1];
            float4 v0 = *(const float4*)(p);
            float4 v1 = *(const float4*)(p + 4);
            float vv[8] = {v0.x, v0.y, v0.z, v0.w, v1.x, v1.y, v1.z, v1.w};
            union { __nv_bfloat16 h[8]; uint4 u; } hh, ll;
#pragma unroll
            for (int j = 0; j < 8; j++) {
                float v = (vv[j] - mu) * rstd;
                __nv_bfloat16 hi = __float2bfloat16_rn(v);
                hh.h[j] = hi;
                ll.h[j] = __float2bfloat16_rn(v - __bfloat162float(hi));
            }
            uint32_t off = sw128((uint32_t)(row * 128 + kc * 2));
            *(uint4*)(sm + SO_A_HI + off) = hh.u;
            *(uint4*)(sm + SO_A_LO + off) = ll.u;
        }
        // --- stage B: 64 n-rows x 64 k of preconverted bf16 hi/lo
#pragma unroll
        for (int gi = 0; gi < 2; gi++) {
            int g   = t + 256 * gi;          // 0..511
            int row = g >> 3;
            int kc  = (g & 7) * 8;
            long src = (long)(n0 + row) * K + k0 + kc;
            uint32_t off = sw128((uint32_t)(row * 128 + kc * 2));
            *(uint4*)(sm + SO_B_HI + off) = *(const uint4*)(Whi + src);
            *(uint4*)(sm + SO_B_LO + off) = *(const uint4*)(Wlo + src);
        }
        __syncthreads();

        const uint32_t sbase = smem_addr(sm);
#pragma unroll
        for (int ks = 0; ks < 4; ks++) {
            const int kb = ks * 16;
            uint32_t ah[2][4], al[2][4], bh[2][4], bl[2][4];
#pragma unroll
            for (int mi = 0; mi < 2; mi++) {
                int row = wm * 32 + mi * 16 + (g8 & 1) * 8 + r8;
                int kc  = kb + (g8 >> 1) * 8;
                uint32_t ad = sbase + sw128((uint32_t)(row * 128 + kc * 2));
                ldsm4(ah[mi], ad + SO_A_HI);
                ldsm4(al[mi], ad + SO_A_LO);
            }
#pragma unroll
            for (int ni = 0; ni < 2; ni++) {
                int row = wn * 32 + ni * 16 + (g8 >> 1) * 8 + r8;
                int kc  = kb + (g8 & 1) * 8;
                uint32_t bd = sbase + sw128((uint32_t)(row * 128 + kc * 2));
                ldsm4(bh[ni], bd + SO_B_HI);
                ldsm4(bl[ni], bd + SO_B_LO);
            }
#pragma unroll
            for (int mi = 0; mi < 2; mi++)
#pragma unroll
                for (int ni = 0; ni < 2; ni++)
#pragma unroll
                    for (int h = 0; h < 2; h++) {
                        float* acc = d[mi][ni * 2 + h];
                        mma16816(acc, ah[mi], &bh[ni][h * 2]);
                        mma16816(acc, al[mi], &bh[ni][h * 2]);
                        mma16816(acc, ah[mi], &bl[ni][h * 2]);
                    }
        }
    }

    // --- epilogue: d reg (q0,q1)->(row lr, col lc,lc+1), (q2,q3)->(row lr+8)
    const int lr = lane >> 2;
    const int lc = (lane & 3) * 2;
#pragma unroll
    for (int mi = 0; mi < 2; mi++) {
#pragma unroll
        for (int half = 0; half < 2; half++) {       // row lr vs lr+8
            int row = m0 + wm * 32 + mi * 16 + lr + half * 8;
            int j0 = 0, j1 = 0, j2 = 0;
            float w0 = 0.f, w1 = 0.f, w2 = 0.f;
            if (INTERP) {
                j0 = g_idx[row * 3 + 0]; j1 = g_idx[row * 3 + 1]; j2 = g_idx[row * 3 + 2];
                w0 = g_wgt[row * 3 + 0]; w1 = g_wgt[row * 3 + 1]; w2 = g_wgt[row * 3 + 2];
            }
            float* crow = C + (long)row * COUT;
#pragma unroll
            for (int nt = 0; nt < 4; nt++) {
                int col = n0 + wn * 32 + nt * 8 + lc;
                float vx = d[mi][nt][half * 2 + 0] + bias[col + 0];
                float vy = d[mi][nt][half * 2 + 1] + bias[col + 1];
                if (INTERP) {
                    float2 h0 = *(const float2*)(g_h + (long)j0 * COUT + col);
                    float2 h1 = *(const float2*)(g_h + (long)j1 * COUT + col);
                    float2 h2 = *(const float2*)(g_h + (long)j2 * COUT + col);
                    vx += w0 * h0.x + w1 * h1.x + w2 * h2.x;
                    vy += w0 * h0.y + w1 * h1.y + w2 * h2.y;
                }
                *(float2*)(crow + col) = make_float2(vx, vy);
            }
        }
    }
}

// ---------------------------------------------------------------------------
// Tail: copy support_xyz and support_offset (value-cast to float) into d_out
// ---------------------------------------------------------------------------
__global__ void tail_kernel(const float* __restrict__ sxyz, const int* __restrict__ soff,
                            float* __restrict__ out)
{
    int i = blockIdx.x * 256 + threadIdx.x;
    if (i < MTOT * 3) out[MTOT * COUT + i] = sxyz[i];
    if (i < B_)       out[MTOT * COUT + MTOT * 3 + i] = (float)soff[i];
}

// ---------------------------------------------------------------------------
extern "C" void kernel_launch(void* const* d_in, const int* in_sizes, int n_in,
                              void* d_out, int out_size)
{
    const float* feats  = (const float*)d_in[0];
    const float* xyz    = (const float*)d_in[1];
    const float* sxyz   = (const float*)d_in[2];
    const float* sfeats = (const float*)d_in[3];
    const int*   soff   = (const int*)  d_in[5];
    const float* ln1_g  = (const float*)d_in[6];
    const float* ln1_b  = (const float*)d_in[7];
    const float* w1     = (const float*)d_in[8];
    const float* b1     = (const float*)d_in[9];
    const float* ln2_g  = (const float*)d_in[10];
    const float* ln2_b  = (const float*)d_in[11];
    const float* w2     = (const float*)d_in[12];
    const float* b2     = (const float*)d_in[13];
    float* out = (float*)d_out;

    static cudaStream_t s2 = nullptr, s3 = nullptr;
    static cudaEvent_t ev_fork = nullptr, ev_j2 = nullptr, ev_j3 = nullptr;
    static bool attr_done = false;
    if (!s2) {
        cudaStreamCreateWithFlags(&s2, cudaStreamNonBlocking);
        cudaStreamCreateWithFlags(&s3, cudaStreamNonBlocking);
        cudaEventCreateWithFlags(&ev_fork, cudaEventDisableTiming);
        cudaEventCreateWithFlags(&ev_j2, cudaEventDisableTiming);
        cudaEventCreateWithFlags(&ev_j3, cudaEventDisableTiming);
    }
    if (!attr_done) {
        cudaFuncSetAttribute(mma_gemm<CIN,  false>, cudaFuncAttributeMaxDynamicSharedMemorySize, SMEM_DYN);
        cudaFuncSetAttribute(mma_gemm<COUT, true >, cudaFuncAttributeMaxDynamicSharedMemorySize, SMEM_DYN);
        attr_done = true;
    }

    float *p_stat_f, *p_stat_s, *p_h, *p_b2p, *p_b1p;
    __nv_bfloat16 *p_w2hi, *p_w2lo, *p_w1hi, *p_w1lo;
    cudaGetSymbolAddress((void**)&p_stat_f, g_stat_f);
    cudaGetSymbolAddress((void**)&p_stat_s, g_stat_s);
    cudaGetSymbolAddress((void**)&p_h,      g_h);
    cudaGetSymbolAddress((void**)&p_b2p,    g_b2p);
    cudaGetSymbolAddress((void**)&p_b1p,    g_b1p);
    cudaGetSymbolAddress((void**)&p_w2hi,   g_w2hi);
    cudaGetSymbolAddress((void**)&p_w2lo,   g_w2lo);
    cudaGetSymbolAddress((void**)&p_w1hi,   g_w1hi);
    cudaGetSymbolAddress((void**)&p_w1lo,   g_w1lo);

    // fork
    cudaEventRecord(ev_fork, 0);
    cudaStreamWaitEvent(s2, ev_fork, 0);
    cudaStreamWaitEvent(s3, ev_fork, 0);

    // s2: kNN + tail (independent of GEMM chain)
    knn_kernel<<<MTOT / 512, 256, 3 * NC * sizeof(float), s2>>>(xyz, sxyz);
    tail_kernel<<<(MTOT * 3 + 255) / 256, 256, 0, s2>>>(sxyz, soff, out);
    cudaEventRecord(ev_j2, s2);

    // s3: stats for branch 1 (only needed by gemm1)
    stats_kernel<COUT><<<MTOT / 8, 256, 0, s3>>>(sfeats, p_stat_s, MTOT);
    cudaEventRecord(ev_j3, s3);

    // main: stats_f + prep -> gemm2
    stats_kernel<CIN><<<NTOT / 8, 256>>>(feats, p_stat_f, NTOT);
    prep_kernel<<<2 * COUT + 2, COUT>>>(w2, ln2_g, ln2_b, b2, w1, ln1_g, ln1_b, b1);
    {
        dim3 grid(COUT / 64, NTOT / 128);
        mma_gemm<CIN, false><<<grid, 256, SMEM_DYN>>>(feats, p_stat_f, p_w2hi, p_w2lo, p_b2p, p_h);
    }

    // join, then gemm1 with fused interp epilogue
    cudaStreamWaitEvent(0, ev_j2, 0);
    cudaStreamWaitEvent(0, ev_j3, 0);
    {
        dim3 grid(COUT / 64, MTOT / 128);
        mma_gemm<COUT, true><<<grid, 256, SMEM_DYN>>>(sfeats, p_stat_s, p_w1hi, p_w1lo, p_b1p, out);
    }
}

// round 6
// speedup vs baseline: 1.0160x; 1.0160x over previous
#include <cuda_runtime.h>
#include <cuda_bf16.h>
#include <cstdint>

// Problem constants (fixed by setup_inputs)
#define B_    4
#define NC    4096      // coarse points per batch
#define MF    16384     // fine points per batch
#define CIN   384
#define COUT  192
#define NTOT  (B_*NC)   // 16384
#define MTOT  (B_*MF)   // 65536

// Scratch (static device globals; allocation-free)
__device__ float g_h[NTOT * COUT];          // branch-2 features at coarse points
__device__ int   g_idx[MTOT * 3];           // 3-NN indices (global coarse index)
__device__ float g_wgt[MTOT * 3];           // 3-NN inverse-distance weights
__device__ float g_stat_f[NTOT * 2];        // per-row (mu, rstd) feats
__device__ float g_stat_s[MTOT * 2];        // per-row (mu, rstd) support_feats
__device__ __align__(16) __nv_bfloat16 g_w2hi[COUT * CIN];   // gamma-folded, transposed [N][K]
__device__ __align__(16) __nv_bfloat16 g_w2lo[COUT * CIN];
__device__ __align__(16) __nv_bfloat16 g_w1hi[COUT * COUT];
__device__ __align__(16) __nv_bfloat16 g_w1lo[COUT * COUT];
__device__ float g_b2p[COUT];               // beta-folded biases
__device__ float g_b1p[COUT];

// ---------------------------------------------------------------------------
// MMA / async helpers (baseline PTX, sm_80+: works on compute_103 target)
// ---------------------------------------------------------------------------
__device__ __forceinline__ void ldsm4(uint32_t* r, uint32_t addr) {
    asm volatile("ldmatrix.sync.aligned.m8n8.x4.shared.b16 {%0,%1,%2,%3}, [%4];"
                 : "=r"(r[0]), "=r"(r[1]), "=r"(r[2]), "=r"(r[3]) : "r"(addr));
}
__device__ __forceinline__ void mma16816(float* d, const uint32_t* a, const uint32_t* b) {
    asm volatile("mma.sync.aligned.m16n8k16.row.col.f32.bf16.bf16.f32 "
                 "{%0,%1,%2,%3}, {%4,%5,%6,%7}, {%8,%9}, {%0,%1,%2,%3};"
                 : "+f"(d[0]), "+f"(d[1]), "+f"(d[2]), "+f"(d[3])
                 : "r"(a[0]), "r"(a[1]), "r"(a[2]), "r"(a[3]), "r"(b[0]), "r"(b[1]));
}
__device__ __forceinline__ void cp_async16(uint32_t saddr, const void* gptr) {
    asm volatile("cp.async.cg.shared.global [%0], [%1], 16;" :: "r"(saddr), "l"(gptr));
}
__device__ __forceinline__ void cp_commit() { asm volatile("cp.async.commit_group;"); }
__device__ __forceinline__ void cp_wait0()  { asm volatile("cp.async.wait_group 0;" ::: "memory"); }
__device__ __forceinline__ uint32_t sw128(uint32_t off) { return off ^ ((off >> 3) & 0x70); }
__device__ __forceinline__ uint32_t smem_addr(const void* p) {
    return (uint32_t)__cvta_generic_to_shared(p);
}

// ---------------------------------------------------------------------------
// Per-row LN statistics: one warp per row -> (mu, rstd)
// ---------------------------------------------------------------------------
template<int C>
__global__ void stats_kernel(const float* __restrict__ x, float* __restrict__ stat, int rows)
{
    int warp = (blockIdx.x * blockDim.x + threadIdx.x) >> 5;
    if (warp >= rows) return;
    int lane = threadIdx.x & 31;
    const float* xr = x + (long)warp * C;
    float s = 0.f, ss = 0.f;
#pragma unroll
    for (int i = 0; i < C / 32; i++) {
        float v = xr[lane + i * 32];
        s += v;
        ss += v * v;
    }
#pragma unroll
    for (int o = 16; o; o >>= 1) {
        s  += __shfl_xor_sync(0xffffffffu, s,  o);
        ss += __shfl_xor_sync(0xffffffffu, ss, o);
    }
    if (lane == 0) {
        float mu  = s * (1.0f / C);
        float var = ss * (1.0f / C) - mu * mu;
        stat[warp * 2 + 0] = mu;
        stat[warp * 2 + 1] = rsqrtf(var + 1e-5f);
    }
}

// ---------------------------------------------------------------------------
// Prep: fold LN gamma into W (transposed [N][K], bf16 hi/lo split) and
// LN beta into bias. grid = 2*COUT + 2 blocks, 192 threads.
// ---------------------------------------------------------------------------
__global__ void prep_kernel(const float* __restrict__ w2, const float* __restrict__ ln2_g,
                            const float* __restrict__ ln2_b, const float* __restrict__ b2,
                            const float* __restrict__ w1, const float* __restrict__ ln1_g,
                            const float* __restrict__ ln1_b, const float* __restrict__ b1)
{
    int bid = blockIdx.x;
    int t = threadIdx.x;
    if (bid < COUT) {                         // w2 row n, K = CIN
        int n = bid;
        for (int k = t; k < CIN; k += COUT) {
            float v = ln2_g[k] * w2[k * COUT + n];
            __nv_bfloat16 hi = __float2bfloat16_rn(v);
            __nv_bfloat16 lo = __float2bfloat16_rn(v - __bfloat162float(hi));
            g_w2hi[n * CIN + k] = hi;
            g_w2lo[n * CIN + k] = lo;
        }
    } else if (bid < 2 * COUT) {              // w1 row n, K = COUT
        int n = bid - COUT;
        for (int k = t; k < COUT; k += COUT) {
            float v = ln1_g[k] * w1[k * COUT + n];
            __nv_bfloat16 hi = __float2bfloat16_rn(v);
            __nv_bfloat16 lo = __float2bfloat16_rn(v - __bfloat162float(hi));
            g_w1hi[n * COUT + k] = hi;
            g_w1lo[n * COUT + k] = lo;
        }
    } else if (bid == 2 * COUT) {
        float s = b2[t];
        for (int k = 0; k < CIN; k++) s = fmaf(ln2_b[k], w2[k * COUT + t], s);
        g_b2p[t] = s;
    } else {
        float s = b1[t];
        for (int k = 0; k < COUT; k++) s = fmaf(ln1_b[k], w1[k * COUT + t], s);
        g_b1p[t] = s;
    }
}

// ---------------------------------------------------------------------------
// Brute-force 3-NN. 2 queries per thread, 512 queries per block.
// ---------------------------------------------------------------------------
__global__ void knn_kernel(const float* __restrict__ cxyz, const float* __restrict__ qxyz)
{
    extern __shared__ char smem_c[];
    float* sx = (float*)smem_c;
    float* sy = sx + NC;
    float* sz = sx + 2 * NC;

    int bidx  = blockIdx.x >> 5;              // 32 blocks of 512 queries per batch
    int chunk = blockIdx.x & 31;
    const float* cb = cxyz + (long)bidx * NC * 3;
    for (int i = threadIdx.x; i < NC; i += 256) {
        sx[i] = cb[i * 3 + 0];
        sy[i] = cb[i * 3 + 1];
        sz[i] = cb[i * 3 + 2];
    }
    __syncthreads();

    int qA = bidx * MF + chunk * 512 + threadIdx.x;
    int qB = qA + 256;
    float ax = qxyz[qA * 3 + 0], ay = qxyz[qA * 3 + 1], az = qxyz[qA * 3 + 2];
    float bx = qxyz[qB * 3 + 0], by = qxyz[qB * 3 + 1], bz = qxyz[qB * 3 + 2];

    float a0 = 1e30f, a1 = 1e30f, a2 = 1e30f; int ai0 = 0, ai1 = 0, ai2 = 0;
    float c0 = 1e30f, c1 = 1e30f, c2 = 1e30f; int ci0 = 0, ci1 = 0, ci2 = 0;

#pragma unroll 8
    for (int j = 0; j < NC; j++) {
        float px = sx[j], py = sy[j], pz = sz[j];
        {
            float dx = ax - px, dy = ay - py, dz = az - pz;
            float d = fmaf(dz, dz, fmaf(dy, dy, dx * dx));
            if (d < a2) {
                if (d < a1) {
                    a2 = a1; ai2 = ai1;
                    if (d < a0) { a1 = a0; ai1 = ai0; a0 = d; ai0 = j; }
                    else        { a1 = d;  ai1 = j; }
                } else { a2 = d; ai2 = j; }
            }
        }
        {
            float dx = bx - px, dy = by - py, dz = bz - pz;
            float d = fmaf(dz, dz, fmaf(dy, dy, dx * dx));
            if (d < c2) {
                if (d < c1) {
                    c2 = c1; ci2 = ci1;
                    if (d < c0) { c1 = c0; ci1 = ci0; c0 = d; ci0 = j; }
                    else        { c1 = d;  ci1 = j; }
                } else { c2 = d; ci2 = j; }
            }
        }
    }

    {
        float r0 = 1.0f / (sqrtf(a0) + 1e-8f);
        float r1 = 1.0f / (sqrtf(a1) + 1e-8f);
        float r2 = 1.0f / (sqrtf(a2) + 1e-8f);
        float rs = 1.0f / (r0 + r1 + r2);
        g_idx[qA * 3 + 0] = bidx * NC + ai0;
        g_idx[qA * 3 + 1] = bidx * NC + ai1;
        g_idx[qA * 3 + 2] = bidx * NC + ai2;
        g_wgt[qA * 3 + 0] = r0 * rs;
        g_wgt[qA * 3 + 1] = r1 * rs;
        g_wgt[qA * 3 + 2] = r2 * rs;
    }
    {
        float r0 = 1.0f / (sqrtf(c0) + 1e-8f);
        float r1 = 1.0f / (sqrtf(c1) + 1e-8f);
        float r2 = 1.0f / (sqrtf(c2) + 1e-8f);
        float rs = 1.0f / (r0 + r1 + r2);
        g_idx[qB * 3 + 0] = bidx * NC + ci0;
        g_idx[qB * 3 + 1] = bidx * NC + ci1;
        g_idx[qB * 3 + 2] = bidx * NC + ci2;
        g_wgt[qB * 3 + 0] = r0 * rs;
        g_wgt[qB * 3 + 1] = r1 * rs;
        g_wgt[qB * 3 + 2] = r2 * rs;
    }
}

// ---------------------------------------------------------------------------
// bf16x3 warp-MMA GEMM, 2-stage pipelined:
//   C[M,192] = LN(A)[M,K] @ W'[K,192] + b'  (+ interp)
// CTA tile 128x64, 8 warps (4 along M x 2 along N), warp tile 32x32, BK=64.
// A: register-prefetch fp32 -> convert bf16 hi/lo at store.  B: cp.async.cg.
// D = Ahi*Bhi + Alo*Bhi + Ahi*Blo.
// ---------------------------------------------------------------------------
#define VO_A_HI  0
#define VO_A_LO  16384
#define VO_B_HI  32768
#define VO_B_LO  40960
#define VSTRIDE  49152
#define SMEM_DYN (2 * VSTRIDE)

template<int K, bool INTERP>
__global__ __launch_bounds__(256)
void mma_gemm(const float* __restrict__ A, const float* __restrict__ stat,
              const __nv_bfloat16* __restrict__ Whi, const __nv_bfloat16* __restrict__ Wlo,
              const float* __restrict__ bias, float* __restrict__ C)
{
    constexpr int KT = K / 64;
    extern __shared__ char smem_c[];
    char* sm = smem_c;

    const int t    = threadIdx.x;
    const int lane = t & 31;
    const int wid  = t >> 5;
    const int wm   = wid & 3;        // warp m-group (0..3)
    const int wn   = wid >> 2;       // warp n-group (0..1)
    const int m0   = blockIdx.y * 128;
    const int n0   = blockIdx.x * 64;
    const int g8   = lane >> 3, r8 = lane & 7;
    const uint32_t sm0 = smem_addr(sm);

    // loader mappings (kt-invariant)
    int arow[4], akc[4];
    float amu[4], ars[4];
    uint32_t aoff[4];
#pragma unroll
    for (int gi = 0; gi < 4; gi++) {
        int g = t + 256 * gi;
        arow[gi] = g >> 3;
        akc[gi]  = (g & 7) * 8;
        amu[gi]  = stat[(m0 + arow[gi]) * 2 + 0];
        ars[gi]  = stat[(m0 + arow[gi]) * 2 + 1];
        aoff[gi] = sw128((uint32_t)(arow[gi] * 128 + akc[gi] * 2));
    }
    int brow[2], bkc[2];
    uint32_t boff[2];
#pragma unroll
    for (int gi = 0; gi < 2; gi++) {
        int g = t + 256 * gi;
        brow[gi] = g >> 3;
        bkc[gi]  = (g & 7) * 8;
        boff[gi] = sw128((uint32_t)(brow[gi] * 128 + bkc[gi] * 2));
    }

    // --- prologue: fill stage 0
#pragma unroll
    for (int gi = 0; gi < 2; gi++) {
        long src = (long)(n0 + brow[gi]) * K + bkc[gi];
        cp_async16(sm0 + VO_B_HI + boff[gi], Whi + src);
        cp_async16(sm0 + VO_B_LO + boff[gi], Wlo + src);
    }
    cp_commit();
#pragma unroll
    for (int gi = 0; gi < 4; gi++) {
        const float* p = A + (long)(m0 + arow[gi]) * K + akc[gi];
        float4 v0 = *(const float4*)(p);
        float4 v1 = *(const float4*)(p + 4);
        float vv[8] = {v0.x, v0.y, v0.z, v0.w, v1.x, v1.y, v1.z, v1.w};
        union { __nv_bfloat16 h[8]; uint4 u; } hh, ll;
#pragma unroll
        for (int j = 0; j < 8; j++) {
            float v = (vv[j] - amu[gi]) * ars[gi];
            __nv_bfloat16 hi = __float2bfloat16_rn(v);
            hh.h[j] = hi;
            ll.h[j] = __float2bfloat16_rn(v - __bfloat162float(hi));
        }
        *(uint4*)(sm + VO_A_HI + aoff[gi]) = hh.u;
        *(uint4*)(sm + VO_A_LO + aoff[gi]) = ll.u;
    }
    cp_wait0();
    __syncthreads();

    float d[2][4][4] = {};
    int s = 0;

#pragma unroll 1
    for (int kt = 0; kt < KT; kt++) {
        const uint32_t sb = (uint32_t)s * VSTRIDE;
        const uint32_t nb = sb ^ VSTRIDE;
        const int k1 = (kt + 1) * 64;
        const bool more = (kt + 1 < KT);

        // kick B prefetch into next stage
        if (more) {
#pragma unroll
            for (int gi = 0; gi < 2; gi++) {
                long src = (long)(n0 + brow[gi]) * K + k1 + bkc[gi];
                cp_async16(sm0 + nb + VO_B_HI + boff[gi], Whi + src);
                cp_async16(sm0 + nb + VO_B_LO + boff[gi], Wlo + src);
            }
            cp_commit();
        }
        // A register prefetch
        float4 pa[4][2];
        if (more) {
#pragma unroll
            for (int gi = 0; gi < 4; gi++) {
                const float* p = A + (long)(m0 + arow[gi]) * K + k1 + akc[gi];
                pa[gi][0] = *(const float4*)(p);
                pa[gi][1] = *(const float4*)(p + 4);
            }
        }

        // --- compute stage s
        const uint32_t sbase = sm0 + sb;
#pragma unroll
        for (int ks = 0; ks < 4; ks++) {
            const int kb = ks * 16;
            uint32_t ah[2][4], al[2][4], bh[2][4], bl[2][4];
#pragma unroll
            for (int mi = 0; mi < 2; mi++) {
                int row = wm * 32 + mi * 16 + (g8 & 1) * 8 + r8;
                int kc  = kb + (g8 >> 1) * 8;
                uint32_t ad = sbase + sw128((uint32_t)(row * 128 + kc * 2));
                ldsm4(ah[mi], ad + VO_A_HI);
                ldsm4(al[mi], ad + VO_A_LO);
            }
#pragma unroll
            for (int ni = 0; ni < 2; ni++) {
                int row = wn * 32 + ni * 16 + (g8 >> 1) * 8 + r8;
                int kc  = kb + (g8 & 1) * 8;
                uint32_t bd = sbase + sw128((uint32_t)(row * 128 + kc * 2));
                ldsm4(bh[ni], bd + VO_B_HI);
                ldsm4(bl[ni], bd + VO_B_LO);
            }
#pragma unroll
            for (int mi = 0; mi < 2; mi++)
#pragma unroll
                for (int ni = 0; ni < 2; ni++)
#pragma unroll
                    for (int h = 0; h < 2; h++) {
                        float* acc = d[mi][ni * 2 + h];
                        mma16816(acc, ah[mi], &bh[ni][h * 2]);
                        mma16816(acc, al[mi], &bh[ni][h * 2]);
                        mma16816(acc, ah[mi], &bl[ni][h * 2]);
                    }
        }

        // --- store A prefetch into next stage
        if (more) {
#pragma unroll
            for (int gi = 0; gi < 4; gi++) {
                float vv[8] = {pa[gi][0].x, pa[gi][0].y, pa[gi][0].z, pa[gi][0].w,
                               pa[gi][1].x, pa[gi][1].y, pa[gi][1].z, pa[gi][1].w};
                union { __nv_bfloat16 h[8]; uint4 u; } hh, ll;
#pragma unroll
                for (int j = 0; j < 8; j++) {
                    float v = (vv[j] - amu[gi]) * ars[gi];
                    __nv_bfloat16 hi = __float2bfloat16_rn(v);
                    hh.h[j] = hi;
                    ll.h[j] = __float2bfloat16_rn(v - __bfloat162float(hi));
                }
                *(uint4*)(sm + nb + VO_A_HI + aoff[gi]) = hh.u;
                *(uint4*)(sm + nb + VO_A_LO + aoff[gi]) = ll.u;
            }
            cp_wait0();
            __syncthreads();
            s ^= 1;
        }
    }

    // --- epilogue: d reg (q0,q1)->(row lr, col lc,lc+1), (q2,q3)->(row lr+8)
    const int lr = lane >> 2;
    const int lc = (lane & 3) * 2;
#pragma unroll
    for (int mi = 0; mi < 2; mi++) {
#pragma unroll
        for (int half = 0; half < 2; half++) {       // row lr vs lr+8
            int row = m0 + wm * 32 + mi * 16 + lr + half * 8;
            int j0 = 0, j1 = 0, j2 = 0;
            float w0 = 0.f, w1 = 0.f, w2 = 0.f;
            if (INTERP) {
                j0 = g_idx[row * 3 + 0]; j1 = g_idx[row * 3 + 1]; j2 = g_idx[row * 3 + 2];
                w0 = g_wgt[row * 3 + 0]; w1 = g_wgt[row * 3 + 1]; w2 = g_wgt[row * 3 + 2];
            }
            float* crow = C + (long)row * COUT;
#pragma unroll
            for (int nt = 0; nt < 4; nt++) {
                int col = n0 + wn * 32 + nt * 8 + lc;
                float vx = d[mi][nt][half * 2 + 0] + bias[col + 0];
                float vy = d[mi][nt][half * 2 + 1] + bias[col + 1];
                if (INTERP) {
                    float2 h0 = *(const float2*)(g_h + (long)j0 * COUT + col);
                    float2 h1 = *(const float2*)(g_h + (long)j1 * COUT + col);
                    float2 h2 = *(const float2*)(g_h + (long)j2 * COUT + col);
                    vx += w0 * h0.x + w1 * h1.x + w2 * h2.x;
                    vy += w0 * h0.y + w1 * h1.y + w2 * h2.y;
                }
                *(float2*)(crow + col) = make_float2(vx, vy);
            }
        }
    }
}

// ---------------------------------------------------------------------------
// Tail: copy support_xyz and support_offset (value-cast to float) into d_out
// ---------------------------------------------------------------------------
__global__ void tail_kernel(const float* __restrict__ sxyz, const int* __restrict__ soff,
                            float* __restrict__ out)
{
    int i = blockIdx.x * 256 + threadIdx.x;
    if (i < MTOT * 3) out[MTOT * COUT + i] = sxyz[i];
    if (i < B_)       out[MTOT * COUT + MTOT * 3 + i] = (float)soff[i];
}

// ---------------------------------------------------------------------------
extern "C" void kernel_launch(void* const* d_in, const int* in_sizes, int n_in,
                              void* d_out, int out_size)
{
    const float* feats  = (const float*)d_in[0];
    const float* xyz    = (const float*)d_in[1];
    const float* sxyz   = (const float*)d_in[2];
    const float* sfeats = (const float*)d_in[3];
    const int*   soff   = (const int*)  d_in[5];
    const float* ln1_g  = (const float*)d_in[6];
    const float* ln1_b  = (const float*)d_in[7];
    const float* w1     = (const float*)d_in[8];
    const float* b1     = (const float*)d_in[9];
    const float* ln2_g  = (const float*)d_in[10];
    const float* ln2_b  = (const float*)d_in[11];
    const float* w2     = (const float*)d_in[12];
    const float* b2     = (const float*)d_in[13];
    float* out = (float*)d_out;

    static cudaStream_t s2 = nullptr, s3 = nullptr;
    static cudaEvent_t ev_fork = nullptr, ev_j2 = nullptr, ev_j3 = nullptr;
    static bool attr_done = false;
    if (!s2) {
        cudaStreamCreateWithFlags(&s2, cudaStreamNonBlocking);
        cudaStreamCreateWithFlags(&s3, cudaStreamNonBlocking);
        cudaEventCreateWithFlags(&ev_fork, cudaEventDisableTiming);
        cudaEventCreateWithFlags(&ev_j2, cudaEventDisableTiming);
        cudaEventCreateWithFlags(&ev_j3, cudaEventDisableTiming);
    }
    if (!attr_done) {
        cudaFuncSetAttribute(mma_gemm<CIN,  false>, cudaFuncAttributeMaxDynamicSharedMemorySize, SMEM_DYN);
        cudaFuncSetAttribute(mma_gemm<COUT, true >, cudaFuncAttributeMaxDynamicSharedMemorySize, SMEM_DYN);
        attr_done = true;
    }

    float *p_stat_f, *p_stat_s, *p_h, *p_b2p, *p_b1p;
    __nv_bfloat16 *p_w2hi, *p_w2lo, *p_w1hi, *p_w1lo;
    cudaGetSymbolAddress((void**)&p_stat_f, g_stat_f);
    cudaGetSymbolAddress((void**)&p_stat_s, g_stat_s);
    cudaGetSymbolAddress((void**)&p_h,      g_h);
    cudaGetSymbolAddress((void**)&p_b2p,    g_b2p);
    cudaGetSymbolAddress((void**)&p_b1p,    g_b1p);
    cudaGetSymbolAddress((void**)&p_w2hi,   g_w2hi);
    cudaGetSymbolAddress((void**)&p_w2lo,   g_w2lo);
    cudaGetSymbolAddress((void**)&p_w1hi,   g_w1hi);
    cudaGetSymbolAddress((void**)&p_w1lo,   g_w1lo);

    // fork
    cudaEventRecord(ev_fork, 0);
    cudaStreamWaitEvent(s2, ev_fork, 0);
    cudaStreamWaitEvent(s3, ev_fork, 0);

    // s2: kNN + tail (independent of GEMM chain)
    knn_kernel<<<MTOT / 512, 256, 3 * NC * sizeof(float), s2>>>(xyz, sxyz);
    tail_kernel<<<(MTOT * 3 + 255) / 256, 256, 0, s2>>>(sxyz, soff, out);
    cudaEventRecord(ev_j2, s2);

    // s3: stats for branch 1 (only needed by gemm1)
    stats_kernel<COUT><<<MTOT / 8, 256, 0, s3>>>(sfeats, p_stat_s, MTOT);
    cudaEventRecord(ev_j3, s3);

    // main: stats_f + prep -> gemm2
    stats_kernel<CIN><<<NTOT / 8, 256>>>(feats, p_stat_f, NTOT);
    prep_kernel<<<2 * COUT + 2, COUT>>>(w2, ln2_g, ln2_b, b2, w1, ln1_g, ln1_b, b1);
    {
        dim3 grid(COUT / 64, NTOT / 128);
        mma_gemm<CIN, false><<<grid, 256, SMEM_DYN>>>(feats, p_stat_f, p_w2hi, p_w2lo, p_b2p, p_h);
    }

    // join, then gemm1 with fused interp epilogue
    cudaStreamWaitEvent(0, ev_j2, 0);
    cudaStreamWaitEvent(0, ev_j3, 0);
    {
        dim3 grid(COUT / 64, MTOT / 128);
        mma_gemm<COUT, true><<<grid, 256, SMEM_DYN>>>(sfeats, p_stat_s, p_w1hi, p_w1lo, p_b1p, out);
    }
}